// round 5
// baseline (speedup 1.0000x reference)
#include <cuda_runtime.h>
#include <math.h>

#define NPTS 16384
#define NSP  4096
#define KNN  11
#define BT   256
#define PPB  (BT / 2)                 // 128 points per block (2 threads/point)

#define GRID  16
#define NCELL (GRID * GRID * GRID)    // 4096
#define CLO   (-4.0f)
#define CH    (0.5f)
#define INVCH (2.0f)

// Scratch (static __device__ arrays: allowed; no allocation)
__device__ float4 g_pts[2][NSP];          // binned spoints: (-2x,-2y,-2z,|s|^2)
__device__ int    g_oid[2][NSP];          // original spoint index per binned entry
__device__ int    g_cs [2][NCELL + 1];    // CSR cell starts (spoints)
__device__ int    g_qid[2][NPTS];         // query ids sorted by cell

__device__ __forceinline__ int clampi(int v, int lo, int hi) {
    return v < lo ? lo : (v > hi ? hi : v);
}
__device__ __forceinline__ int cell1d(float v) {
    return clampi((int)floorf((v - CLO) * INVCH), 0, GRID - 1);
}

// Monotone float->uint mapping (order-preserving for all finite floats)
__device__ __forceinline__ unsigned fkey(float f) {
    unsigned b = __float_as_uint(f);
    return b ^ ((unsigned)((int)b >> 31) | 0x80000000u);
}
__device__ __forceinline__ float funkey(unsigned u) {
    unsigned b = (u & 0x80000000u) ? (u ^ 0x80000000u) : ~u;
    return __uint_as_float(b);
}
#define SENTINEL 0xFF800000FFFFFFFFull   // upper = fkey(+inf)

// ---------------------------------------------------------------------------
// Kernel 1: bin spoints of one batch into the 16^3 grid (1 block per batch)
// ---------------------------------------------------------------------------
__global__ void __launch_bounds__(1024) bin_kernel(const float* __restrict__ spoints) {
    const int b = blockIdx.x;
    const int t = threadIdx.x;

    __shared__ int cnt[NCELL];
    __shared__ int start[NCELL];
    __shared__ int part[1024];

    for (int i = t; i < NCELL; i += 1024) cnt[i] = 0;
    __syncthreads();

    const float* sp = spoints + (size_t)b * NSP * 3;
    for (int j = t; j < NSP; j += 1024) {
        int cx = cell1d(sp[3 * j + 0]);
        int cy = cell1d(sp[3 * j + 1]);
        int cz = cell1d(sp[3 * j + 2]);
        atomicAdd(&cnt[(cz * GRID + cy) * GRID + cx], 1);
    }
    __syncthreads();

    // Exclusive scan over 4096 counters (each thread owns 4 consecutive)
    int v0 = cnt[t * 4 + 0], v1 = cnt[t * 4 + 1];
    int v2 = cnt[t * 4 + 2], v3 = cnt[t * 4 + 3];
    int s = v0 + v1 + v2 + v3;
    part[t] = s;
    __syncthreads();
    for (int off = 1; off < 1024; off <<= 1) {
        int x = (t >= off) ? part[t - off] : 0;
        __syncthreads();
        part[t] += x;
        __syncthreads();
    }
    int base = part[t] - s;
    start[t * 4 + 0] = base;               base += v0;
    start[t * 4 + 1] = base;               base += v1;
    start[t * 4 + 2] = base;               base += v2;
    start[t * 4 + 3] = base;
    __syncthreads();

    for (int i = t; i < NCELL; i += 1024) {
        g_cs[b][i] = start[i];
        cnt[i] = start[i];                 // reuse cnt as scatter cursor
    }
    if (t == 0) g_cs[b][NCELL] = NSP;
    __syncthreads();

    for (int j = t; j < NSP; j += 1024) {
        float x = sp[3 * j + 0];
        float y = sp[3 * j + 1];
        float z = sp[3 * j + 2];
        int c = (cell1d(z) * GRID + cell1d(y)) * GRID + cell1d(x);
        int pos = atomicAdd(&cnt[c], 1);
        g_pts[b][pos] = make_float4(-2.0f * x, -2.0f * y, -2.0f * z,
                                    fmaf(x, x, fmaf(y, y, z * z)));
        g_oid[b][pos] = j;
    }
}

// ---------------------------------------------------------------------------
// Kernel 1b: sort query points by cell (1 block per batch)
// ---------------------------------------------------------------------------
__global__ void __launch_bounds__(1024) qbin_kernel(const float* __restrict__ points) {
    const int b = blockIdx.x;
    const int t = threadIdx.x;

    __shared__ int cnt[NCELL];
    __shared__ int start[NCELL];
    __shared__ int part[1024];

    for (int i = t; i < NCELL; i += 1024) cnt[i] = 0;
    __syncthreads();

    const float* pp = points + (size_t)b * NPTS * 3;
    for (int j = t; j < NPTS; j += 1024) {
        int cx = cell1d(pp[3 * j + 0]);
        int cy = cell1d(pp[3 * j + 1]);
        int cz = cell1d(pp[3 * j + 2]);
        atomicAdd(&cnt[(cz * GRID + cy) * GRID + cx], 1);
    }
    __syncthreads();

    int v0 = cnt[t * 4 + 0], v1 = cnt[t * 4 + 1];
    int v2 = cnt[t * 4 + 2], v3 = cnt[t * 4 + 3];
    int s = v0 + v1 + v2 + v3;
    part[t] = s;
    __syncthreads();
    for (int off = 1; off < 1024; off <<= 1) {
        int x = (t >= off) ? part[t - off] : 0;
        __syncthreads();
        part[t] += x;
        __syncthreads();
    }
    int base = part[t] - s;
    start[t * 4 + 0] = base;               base += v0;
    start[t * 4 + 1] = base;               base += v1;
    start[t * 4 + 2] = base;               base += v2;
    start[t * 4 + 3] = base;
    __syncthreads();

    for (int i = t; i < NCELL; i += 1024) cnt[i] = start[i];
    __syncthreads();

    for (int j = t; j < NPTS; j += 1024) {
        int cx = cell1d(pp[3 * j + 0]);
        int cy = cell1d(pp[3 * j + 1]);
        int cz = cell1d(pp[3 * j + 2]);
        int c = (cz * GRID + cy) * GRID + cx;
        int pos = atomicAdd(&cnt[c], 1);
        g_qid[b][pos] = j;
    }
}

// ---------------------------------------------------------------------------
// Kernel 2: exact 11-NN, 2 threads/point (even/odd candidate split),
//           ring expansion with per-cell lower bounds + Voronoi epilogue
// ---------------------------------------------------------------------------
__global__ void __launch_bounds__(BT) voro_kernel(
    const float* __restrict__ points,
    const float* __restrict__ spoints,
    float* __restrict__ out)
{
    const int tid = threadIdx.x;
    const int s   = tid & 1;                       // half-id within the pair
    const int pl  = tid >> 1;                      // local point 0..127
    const int gp  = blockIdx.x * PPB + pl;         // sorted point slot
    const int b   = gp >> 14;                      // gp / NPTS
    const int q   = g_qid[b][gp & (NPTS - 1)];     // original query index

    const float* pp = points + ((size_t)b * NPTS + q) * 3;
    const float px = pp[0], py = pp[1], pz = pp[2];
    const float p2 = fmaf(px, px, fmaf(py, py, pz * pz));

    const float4* __restrict__ pts = g_pts[b];
    const int*    __restrict__ oid = g_oid[b];
    const int*    __restrict__ cs  = g_cs[b];

    const int cx = cell1d(px), cy = cell1d(py), cz = cell1d(pz);

    unsigned long long best[KNN];
#pragma unroll
    for (int k = 0; k < KNN; ++k) best[k] = SENTINEL;
    float worst_e  = __int_as_float(0x7f800000);   // +inf  (e = d2 - p2 ordering)
    float worst_d2 = __int_as_float(0x7f800000);

#define SCAN_CELL(c)                                                          \
    {                                                                         \
        int _s0 = __ldg(&cs[(c)]);                                            \
        int _s1 = __ldg(&cs[(c) + 1]);                                        \
        for (int _k = _s0 + s; _k < _s1; _k += 2) {                           \
            float4 qq = __ldg(&pts[_k]);                                      \
            float e = fmaf(qq.x, px, fmaf(qq.y, py, fmaf(qq.z, pz, qq.w)));   \
            if (e <= worst_e) {                                               \
                unsigned long long key =                                      \
                    ((unsigned long long)fkey(e) << 32) | (unsigned)__ldg(&oid[_k]); \
                if (key < best[KNN - 1]) {                                    \
                    best[KNN - 1] = key;                                      \
                    _Pragma("unroll")                                         \
                    for (int _m = KNN - 1; _m > 0; --_m) {                    \
                        if (best[_m] < best[_m - 1]) {                        \
                            unsigned long long _t = best[_m];                 \
                            best[_m] = best[_m - 1];                          \
                            best[_m - 1] = _t;                                \
                        }                                                     \
                    }                                                         \
                    worst_e  = funkey((unsigned)(best[KNN - 1] >> 32));       \
                    worst_d2 = worst_e + p2;                                  \
                }                                                             \
            }                                                                 \
        }                                                                     \
    }

    // Ring 0: own cell
    SCAN_CELL((cz * GRID + cy) * GRID + cx);

    for (int r = 0; ; ++r) {
        float m = __int_as_float(0x7f800000);
        if (cx - r > 0)        m = fminf(m, px - (CLO + (cx - r) * CH));
        if (cx + r < GRID - 1) m = fminf(m, (CLO + (cx + r + 1) * CH) - px);
        if (cy - r > 0)        m = fminf(m, py - (CLO + (cy - r) * CH));
        if (cy + r < GRID - 1) m = fminf(m, (CLO + (cy + r + 1) * CH) - py);
        if (cz - r > 0)        m = fminf(m, pz - (CLO + (cz - r) * CH));
        if (cz + r < GRID - 1) m = fminf(m, (CLO + (cz + r + 1) * CH) - pz);
        if (worst_d2 <= m * m * 0.99999f) break;
        if (r >= GRID - 1) break;

        const int rr = r + 1;
        const int z0 = max(cz - rr, 0), z1 = min(cz + rr, GRID - 1);
        const int y0 = max(cy - rr, 0), y1 = min(cy + rr, GRID - 1);
        const int x0 = max(cx - rr, 0), x1 = min(cx + rr, GRID - 1);
        for (int zz = z0; zz <= z1; ++zz) {
            for (int yy = y0; yy <= y1; ++yy) {
                for (int xx = x0; xx <= x1; ++xx) {
                    int ch = max(abs(zz - cz), max(abs(yy - cy), abs(xx - cx)));
                    if (ch != rr) continue;
                    float clo, dx, dy, dz;
                    clo = CLO + xx * CH;
                    dx = fmaxf(0.0f, fmaxf(clo - px, px - (clo + CH)));
                    clo = CLO + yy * CH;
                    dy = fmaxf(0.0f, fmaxf(clo - py, py - (clo + CH)));
                    clo = CLO + zz * CH;
                    dz = fmaxf(0.0f, fmaxf(clo - pz, pz - (clo + CH)));
                    float d2c = fmaf(dx, dx, fmaf(dy, dy, dz * dz));
                    if (d2c * 0.99999f > worst_d2) continue;
                    SCAN_CELL((zz * GRID + yy) * GRID + xx);
                }
            }
        }
    }
#undef SCAN_CELL

    // Pair merge: fetch partner's sorted list, merge two sorted 11-lists.
    unsigned long long other[KNN];
#pragma unroll
    for (int k = 0; k < KNN; ++k)
        other[k] = __shfl_xor_sync(0xFFFFFFFFu, best[k], 1);

    if (s == 0) {
        unsigned long long top[KNN];
        int i = 0, j = 0;
#pragma unroll
        for (int k = 0; k < KNN; ++k) {
            unsigned long long a = best[i], c = other[j];
            if (a <= c) { top[k] = a; ++i; } else { top[k] = c; ++j; }
        }

        // Epilogue: min over 10 Voronoi edges of (dot(v,e) - |e|^2/2)^2 / |e|^2
        const float* sp = spoints + (size_t)b * NSP * 3;
        const int i0 = (int)(top[0] & 0xFFFFFFFFull);
        float cx0 = __ldg(sp + 3 * i0 + 0);
        float cy0 = __ldg(sp + 3 * i0 + 1);
        float cz0 = __ldg(sp + 3 * i0 + 2);
        float vx = px - cx0, vy = py - cy0, vz = pz - cz0;
        float mmin = __int_as_float(0x7f800000);
#pragma unroll
        for (int k = 1; k < KNN; ++k) {
            const int ik = (int)(top[k] & 0xFFFFFFFFull);
            float ex = __ldg(sp + 3 * ik + 0) - cx0;
            float ey = __ldg(sp + 3 * ik + 1) - cy0;
            float ez = __ldg(sp + 3 * ik + 2) - cz0;
            float el2 = fmaf(ex, ex, fmaf(ey, ey, ez * ez));
            float dve = fmaf(vx, ex, fmaf(vy, ey, vz * ez));
            float u   = fmaf(-0.5f, el2, dve);
            mmin = fminf(mmin, (u * u) / el2);
        }
        out[(size_t)b * NPTS + q] = mmin;
    }
}

extern "C" void kernel_launch(void* const* d_in, const int* in_sizes, int n_in,
                              void* d_out, int out_size) {
    const float* points  = (const float*)d_in[0];   // (2, 16384, 3) f32
    const float* spoints = (const float*)d_in[1];   // (2, 4096, 3)  f32
    float* out = (float*)d_out;                     // (2, 16384)    f32

    bin_kernel<<<2, 1024>>>(spoints);
    qbin_kernel<<<2, 1024>>>(points);
    voro_kernel<<<(2 * NPTS) / PPB, BT>>>(points, spoints, out);
}

// round 6
// speedup vs baseline: 1.7330x; 1.7330x over previous
#include <cuda_runtime.h>
#include <math.h>

#define NPTS 16384
#define NSP  4096
#define KNN  11
#define BT   128

#define GRID  16
#define NCELL (GRID * GRID * GRID)    // 4096
#define CLO   (-4.0f)
#define CH    (0.5f)
#define INVCH (2.0f)

// Scratch (static __device__ arrays: allowed; no allocation)
__device__ float4 g_pts[2][NSP];          // binned spoints: (-2x,-2y,-2z,|s|^2)
__device__ int    g_oid[2][NSP];          // original spoint index per binned entry
__device__ int    g_cs [2][NCELL + 1];    // CSR cell starts (spoints)
__device__ int    g_qid[2][NPTS];         // query ids sorted by cell

__device__ __forceinline__ int clampi(int v, int lo, int hi) {
    return v < lo ? lo : (v > hi ? hi : v);
}
__device__ __forceinline__ int cell1d(float v) {
    return clampi((int)floorf((v - CLO) * INVCH), 0, GRID - 1);
}

// Monotone float->uint mapping (order-preserving for all finite floats)
__device__ __forceinline__ unsigned fkey(float f) {
    unsigned b = __float_as_uint(f);
    return b ^ ((unsigned)((int)b >> 31) | 0x80000000u);
}
__device__ __forceinline__ float funkey(unsigned u) {
    unsigned b = (u & 0x80000000u) ? (u ^ 0x80000000u) : ~u;
    return __uint_as_float(b);
}
#define SENTINEL 0xFF800000FFFFFFFFull   // upper = fkey(+inf)

// ---------------------------------------------------------------------------
// Kernel 1: bin spoints of one batch into the 16^3 grid (1 block per batch)
// ---------------------------------------------------------------------------
__global__ void __launch_bounds__(1024) bin_kernel(const float* __restrict__ spoints) {
    const int b = blockIdx.x;
    const int t = threadIdx.x;

    __shared__ int cnt[NCELL];
    __shared__ int start[NCELL];
    __shared__ int part[1024];

    for (int i = t; i < NCELL; i += 1024) cnt[i] = 0;
    __syncthreads();

    const float* sp = spoints + (size_t)b * NSP * 3;
    for (int j = t; j < NSP; j += 1024) {
        int cx = cell1d(sp[3 * j + 0]);
        int cy = cell1d(sp[3 * j + 1]);
        int cz = cell1d(sp[3 * j + 2]);
        atomicAdd(&cnt[(cz * GRID + cy) * GRID + cx], 1);
    }
    __syncthreads();

    // Exclusive scan over 4096 counters (each thread owns 4 consecutive)
    int v0 = cnt[t * 4 + 0], v1 = cnt[t * 4 + 1];
    int v2 = cnt[t * 4 + 2], v3 = cnt[t * 4 + 3];
    int s = v0 + v1 + v2 + v3;
    part[t] = s;
    __syncthreads();
    for (int off = 1; off < 1024; off <<= 1) {
        int x = (t >= off) ? part[t - off] : 0;
        __syncthreads();
        part[t] += x;
        __syncthreads();
    }
    int base = part[t] - s;
    start[t * 4 + 0] = base;               base += v0;
    start[t * 4 + 1] = base;               base += v1;
    start[t * 4 + 2] = base;               base += v2;
    start[t * 4 + 3] = base;
    __syncthreads();

    for (int i = t; i < NCELL; i += 1024) {
        g_cs[b][i] = start[i];
        cnt[i] = start[i];                 // reuse cnt as scatter cursor
    }
    if (t == 0) g_cs[b][NCELL] = NSP;
    __syncthreads();

    for (int j = t; j < NSP; j += 1024) {
        float x = sp[3 * j + 0];
        float y = sp[3 * j + 1];
        float z = sp[3 * j + 2];
        int c = (cell1d(z) * GRID + cell1d(y)) * GRID + cell1d(x);
        int pos = atomicAdd(&cnt[c], 1);
        g_pts[b][pos] = make_float4(-2.0f * x, -2.0f * y, -2.0f * z,
                                    fmaf(x, x, fmaf(y, y, z * z)));
        g_oid[b][pos] = j;
    }
}

// ---------------------------------------------------------------------------
// Kernel 1b: sort query points by cell (1 block per batch)
// ---------------------------------------------------------------------------
__global__ void __launch_bounds__(1024) qbin_kernel(const float* __restrict__ points) {
    const int b = blockIdx.x;
    const int t = threadIdx.x;

    __shared__ int cnt[NCELL];
    __shared__ int start[NCELL];
    __shared__ int part[1024];

    for (int i = t; i < NCELL; i += 1024) cnt[i] = 0;
    __syncthreads();

    const float* pp = points + (size_t)b * NPTS * 3;
    for (int j = t; j < NPTS; j += 1024) {
        int cx = cell1d(pp[3 * j + 0]);
        int cy = cell1d(pp[3 * j + 1]);
        int cz = cell1d(pp[3 * j + 2]);
        atomicAdd(&cnt[(cz * GRID + cy) * GRID + cx], 1);
    }
    __syncthreads();

    int v0 = cnt[t * 4 + 0], v1 = cnt[t * 4 + 1];
    int v2 = cnt[t * 4 + 2], v3 = cnt[t * 4 + 3];
    int s = v0 + v1 + v2 + v3;
    part[t] = s;
    __syncthreads();
    for (int off = 1; off < 1024; off <<= 1) {
        int x = (t >= off) ? part[t - off] : 0;
        __syncthreads();
        part[t] += x;
        __syncthreads();
    }
    int base = part[t] - s;
    start[t * 4 + 0] = base;               base += v0;
    start[t * 4 + 1] = base;               base += v1;
    start[t * 4 + 2] = base;               base += v2;
    start[t * 4 + 3] = base;
    __syncthreads();

    for (int i = t; i < NCELL; i += 1024) cnt[i] = start[i];
    __syncthreads();

    for (int j = t; j < NPTS; j += 1024) {
        int cx = cell1d(pp[3 * j + 0]);
        int cy = cell1d(pp[3 * j + 1]);
        int cz = cell1d(pp[3 * j + 2]);
        int c = (cz * GRID + cy) * GRID + cx;
        int pos = atomicAdd(&cnt[c], 1);
        g_qid[b][pos] = j;
    }
}

// ---------------------------------------------------------------------------
// Kernel 2: exact 11-NN via expanding rings, 1 thread/point, queries sorted
//           by cell so warps are spatially coherent. Voronoi epilogue.
// ---------------------------------------------------------------------------
__global__ void __launch_bounds__(BT) voro_kernel(
    const float* __restrict__ points,
    const float* __restrict__ spoints,
    float* __restrict__ out)
{
    const int gp = blockIdx.x * BT + threadIdx.x;  // sorted slot
    const int b  = gp >> 14;                       // gp / NPTS
    const int q  = g_qid[b][gp & (NPTS - 1)];      // original query index

    const float* pp = points + ((size_t)b * NPTS + q) * 3;
    const float px = pp[0], py = pp[1], pz = pp[2];
    const float p2 = fmaf(px, px, fmaf(py, py, pz * pz));

    const float4* __restrict__ pts = g_pts[b];
    const int*    __restrict__ oid = g_oid[b];
    const int*    __restrict__ cs  = g_cs[b];

    const int cx = cell1d(px), cy = cell1d(py), cz = cell1d(pz);

    unsigned long long best[KNN];
#pragma unroll
    for (int k = 0; k < KNN; ++k) best[k] = SENTINEL;
    float worst_e  = __int_as_float(0x7f800000);   // +inf  (e = d2 - p2 ordering)
    float worst_d2 = __int_as_float(0x7f800000);

#define SCAN_CELL(c)                                                          \
    {                                                                         \
        int _s0 = __ldg(&cs[(c)]);                                            \
        int _s1 = __ldg(&cs[(c) + 1]);                                        \
        for (int _k = _s0; _k < _s1; ++_k) {                                  \
            float4 qq = __ldg(&pts[_k]);                                      \
            float e = fmaf(qq.x, px, fmaf(qq.y, py, fmaf(qq.z, pz, qq.w)));   \
            if (e <= worst_e) {                                               \
                unsigned long long key =                                      \
                    ((unsigned long long)fkey(e) << 32) | (unsigned)__ldg(&oid[_k]); \
                if (key < best[KNN - 1]) {                                    \
                    best[KNN - 1] = key;                                      \
                    _Pragma("unroll")                                         \
                    for (int _m = KNN - 1; _m > 0; --_m) {                    \
                        if (best[_m] < best[_m - 1]) {                        \
                            unsigned long long _t = best[_m];                 \
                            best[_m] = best[_m - 1];                          \
                            best[_m - 1] = _t;                                \
                        }                                                     \
                    }                                                         \
                    worst_e  = funkey((unsigned)(best[KNN - 1] >> 32));       \
                    worst_d2 = worst_e + p2;                                  \
                }                                                             \
            }                                                                 \
        }                                                                     \
    }

    // Ring 0: own cell
    SCAN_CELL((cz * GRID + cy) * GRID + cx);

    for (int r = 0; ; ++r) {
        // Min possible distance from p to any cell beyond the scanned cube.
        // Faces clipped at the grid edge contribute +inf (candidates clamped inside).
        float m = __int_as_float(0x7f800000);
        if (cx - r > 0)        m = fminf(m, px - (CLO + (cx - r) * CH));
        if (cx + r < GRID - 1) m = fminf(m, (CLO + (cx + r + 1) * CH) - px);
        if (cy - r > 0)        m = fminf(m, py - (CLO + (cy - r) * CH));
        if (cy + r < GRID - 1) m = fminf(m, (CLO + (cy + r + 1) * CH) - py);
        if (cz - r > 0)        m = fminf(m, pz - (CLO + (cz - r) * CH));
        if (cz + r < GRID - 1) m = fminf(m, (CLO + (cz + r + 1) * CH) - pz);
        if (worst_d2 <= m * m * 0.99999f) break;
        if (r >= GRID - 1) break;

        const int rr = r + 1;
        const int z0 = max(cz - rr, 0), z1 = min(cz + rr, GRID - 1);
        const int y0 = max(cy - rr, 0), y1 = min(cy + rr, GRID - 1);
        const int x0 = max(cx - rr, 0), x1 = min(cx + rr, GRID - 1);
        for (int zz = z0; zz <= z1; ++zz) {
            for (int yy = y0; yy <= y1; ++yy) {
                for (int xx = x0; xx <= x1; ++xx) {
                    int ch = max(abs(zz - cz), max(abs(yy - cy), abs(xx - cx)));
                    if (ch != rr) continue;   // cube surface only
                    float clo, dx, dy, dz;
                    clo = CLO + xx * CH;
                    dx = fmaxf(0.0f, fmaxf(clo - px, px - (clo + CH)));
                    clo = CLO + yy * CH;
                    dy = fmaxf(0.0f, fmaxf(clo - py, py - (clo + CH)));
                    clo = CLO + zz * CH;
                    dz = fmaxf(0.0f, fmaxf(clo - pz, pz - (clo + CH)));
                    float d2c = fmaf(dx, dx, fmaf(dy, dy, dz * dz));
                    if (d2c * 0.99999f > worst_d2) continue;
                    SCAN_CELL((zz * GRID + yy) * GRID + xx);
                }
            }
        }
    }
#undef SCAN_CELL

    // Epilogue: min over 10 Voronoi edges of (dot(v,e) - |e|^2/2)^2 / |e|^2
    const float* sp = spoints + (size_t)b * NSP * 3;
    const int i0 = (int)(best[0] & 0xFFFFFFFFull);
    float cx0 = __ldg(sp + 3 * i0 + 0);
    float cy0 = __ldg(sp + 3 * i0 + 1);
    float cz0 = __ldg(sp + 3 * i0 + 2);
    float vx = px - cx0, vy = py - cy0, vz = pz - cz0;
    float mmin = __int_as_float(0x7f800000);
#pragma unroll
    for (int k = 1; k < KNN; ++k) {
        const int ik = (int)(best[k] & 0xFFFFFFFFull);
        float ex = __ldg(sp + 3 * ik + 0) - cx0;
        float ey = __ldg(sp + 3 * ik + 1) - cy0;
        float ez = __ldg(sp + 3 * ik + 2) - cz0;
        float el2 = fmaf(ex, ex, fmaf(ey, ey, ez * ez));
        float dve = fmaf(vx, ex, fmaf(vy, ey, vz * ez));
        float u   = fmaf(-0.5f, el2, dve);
        mmin = fminf(mmin, (u * u) / el2);
    }
    out[(size_t)b * NPTS + q] = mmin;
}

extern "C" void kernel_launch(void* const* d_in, const int* in_sizes, int n_in,
                              void* d_out, int out_size) {
    const float* points  = (const float*)d_in[0];   // (2, 16384, 3) f32
    const float* spoints = (const float*)d_in[1];   // (2, 4096, 3)  f32
    float* out = (float*)d_out;                     // (2, 16384)    f32

    bin_kernel<<<2, 1024>>>(spoints);
    qbin_kernel<<<2, 1024>>>(points);
    voro_kernel<<<(2 * NPTS) / BT, BT>>>(points, spoints, out);
}